// round 14
// baseline (speedup 1.0000x reference)
#include <cuda_runtime.h>
#include <cstddef>

// Problem constants (fixed by setup_inputs)
constexpr int B = 8;
constexpr int C = 144;
constexpr int N = 4096;
constexpr int K = 16;
constexpr int G = 9;
constexpr int D = 16;          // C / G
constexpr int NTILE = 64;      // points per transpose block
constexpr int NBLK_N = N / NTILE;

constexpr int FEAT_ELEMS = B * C * N;      // 4718592
constexpr int CENT_ELEMS = B * G * N;      // 294912
constexpr int IDX_ELEMS  = B * N * K;      // 524288
constexpr int TBLOCKS    = B * G * NBLK_N; // 4608 (= CENT_ELEMS / 64)

constexpr int PTS     = 64;                // points per attn block (4 lanes each)
constexpr int NBLK_A  = N / PTS;           // 64
constexpr int ABLOCKS = B * G * NBLK_A;    // 4608

// Fused scratch: per point one 128B row = [key(16 floats) | value(16 floats)].
__device__ __align__(128) float g_qkv[(size_t)B * G * N * 32];

// Index-dtype flag: 1 if idx_knn is int64, 0 if int32.
__device__ int g_idx_is64;

// ---------------------------------------------------------------------------
// Transpose (B, C, N) -> fused (B*G, N, 32) rows, zero the centrality region,
// and (block 0 only) detect the idx dtype.
// ---------------------------------------------------------------------------
__global__ void __launch_bounds__(256) transpose_kernel(
    const float* __restrict__ qk, const float* __restrict__ val,
    const unsigned int* __restrict__ idx_raw,
    float* __restrict__ cent)
{
    __shared__ float tile[D][NTILE + 1];
    __shared__ unsigned int s_any;

    const int blk   = blockIdx.x;
    const int ntile = blk % NBLK_N;
    const int bg    = blk / NBLK_N;
    const int g     = bg % G;
    const int b     = bg / G;
    const int n0    = ntile * NTILE;
    const int tid   = threadIdx.x;

    // ---- block 0: idx dtype detection (odd words all zero => int64) ----
    if (blk == 0) {
        if (tid == 0) s_any = 0u;
        __syncthreads();
        unsigned int v = idx_raw[2 * tid + 1] |
                         idx_raw[2 * (tid + 256) + 1] |
                         idx_raw[2 * (tid + 512) + 1] |
                         idx_raw[2 * (tid + 768) + 1];
        if (v) atomicOr(&s_any, 1u);
        __syncthreads();
        if (tid == 0) g_idx_is64 = (s_any == 0u) ? 1 : 0;
    }

    // ---- zero this block's 64-element slice of centrality ----
    if (cent != nullptr && tid < 64)
        cent[(size_t)blk * 64 + tid] = 0.0f;

    const size_t src_off = ((size_t)b * C + (size_t)g * D) * N + n0;
    float* dst = g_qkv + ((size_t)bg * N + n0) * 32;

    {   // queryandkey -> row offset [0:16)
        const float* src = qk + src_off;
        #pragma unroll
        for (int r = 0; r < 4; r++) {
            int e = tid + r * 256;
            int j = e >> 6, nn = e & 63;
            tile[j][nn] = src[(size_t)j * N + nn];
        }
        __syncthreads();
        #pragma unroll
        for (int r = 0; r < 4; r++) {
            int e = tid + r * 256;
            int nn = e >> 4, j = e & 15;
            dst[nn * 32 + j] = tile[j][nn];
        }
        __syncthreads();
    }
    {   // value -> row offset [16:32)
        const float* src = val + src_off;
        #pragma unroll
        for (int r = 0; r < 4; r++) {
            int e = tid + r * 256;
            int j = e >> 6, nn = e & 63;
            tile[j][nn] = src[(size_t)j * N + nn];
        }
        __syncthreads();
        #pragma unroll
        for (int r = 0; r < 4; r++) {
            int e = tid + r * 256;
            int nn = e >> 4, j = e & 15;
            dst[nn * 32 + 16 + j] = tile[j][nn];
        }
    }
}

// ---------------------------------------------------------------------------
// Fused attention, 4 lanes per point (32B per lane):
//   lane 0: key[0:8]   lane 1: key[8:16]   lane 2: val[0:8]   lane 3: val[8:16]
// One neighbor row (128B line) is fetched by its 4-lane group as 2 float4
// loads per lane-pair; a warp serves 8 points, so per-point shuffle / exp /
// LDS cost halves-to-thirds vs the 8-lane scheme (R10-R13 plateau).
// Dot reduction: zero value-lane partials, xor1 + xor2 -> all 4 lanes.
// Softmax shifted by the first logit (shift-invariant, no max pre-pass).
// ---------------------------------------------------------------------------
__global__ void __launch_bounds__(256, 4) attn_kernel(
    const void* __restrict__ idx_raw,
    float* __restrict__ out,           // feature region
    float* __restrict__ cent)          // centrality region (may be null)
{
    __shared__ int   s_off[PTS][17];    // [point][k]: neighbor byte offsets
    __shared__ float ftile[PTS][D + 1];

    const int blk = blockIdx.x;
    const int nt  = blk % NBLK_A;
    const int bg  = blk / NBLK_A;
    const int g   = bg % G;
    const int b   = bg / G;
    const int n0  = nt * PTS;

    const int tid = threadIdx.x;
    const int p   = tid >> 2;           // point within block (0..63)
    const int L   = tid & 3;            // lane within point (0..3)
    const int n   = n0 + p;
    const unsigned FULL = 0xffffffffu;

    const float keysel = (L < 2) ? 1.0f : 0.0f;   // value lanes contribute 0

    const size_t bgN = (size_t)bg * N;

    // --- lane L loads neighbors 4L..4L+3 (dtype-dispatched), clamp ---
    const size_t ibase = ((size_t)b * N + n) * K + 4 * L;
    int mi[4];
    if (g_idx_is64) {
        const long long* ip = reinterpret_cast<const long long*>(idx_raw) + ibase;
        longlong2 e0 = *reinterpret_cast<const longlong2*>(ip);
        longlong2 e1 = *reinterpret_cast<const longlong2*>(ip + 2);
        mi[0] = (int)e0.x; mi[1] = (int)e0.y; mi[2] = (int)e1.x; mi[3] = (int)e1.y;
    } else {
        int4 e = *reinterpret_cast<const int4*>(
            reinterpret_cast<const int*>(idx_raw) + ibase);
        mi[0] = e.x; mi[1] = e.y; mi[2] = e.z; mi[3] = e.w;
    }
    #pragma unroll
    for (int i = 0; i < 4; i++) {
        mi[i] = min(max(mi[i], 0), N - 1);
        s_off[p][4 * L + i] = mi[i] << 7;   // 128 bytes per point row
    }
    __syncwarp();

    // Gather base pointer: folds bg-slab and this lane's 32B sub-offset.
    const char* gbase = reinterpret_cast<const char*>(g_qkv)
                      + bgN * 128 + (size_t)L * 32;

    // --- query halves (key lanes use q[8L'..]; value lanes mirror, unused) ---
    const char* qrow = reinterpret_cast<const char*>(g_qkv)
                     + (bgN + n) * 128 + (size_t)(L & 1) * 32;
    const float4 q0 = *reinterpret_cast<const float4*>(qrow);
    const float4 q1 = *reinterpret_cast<const float4*>(qrow + 16);

    // --- single pass, depth-2 pipelined gathers (2 float4 per k) ---
    float s0 = 0.0f;                    // shift = first logit
    float sum = 0.0f;
    float my_e[4] = {0.f, 0.f, 0.f, 0.f};  // exps of this lane's 4 neighbors
    float4 acc0 = make_float4(0.f, 0.f, 0.f, 0.f);
    float4 acc1 = make_float4(0.f, 0.f, 0.f, 0.f);

    float4 kva0 = *reinterpret_cast<const float4*>(gbase + s_off[p][0]);
    float4 kva1 = *reinterpret_cast<const float4*>(gbase + s_off[p][0] + 16);

    #pragma unroll
    for (int k = 0; k < 16; k++) {
        float4 kv0 = kva0, kv1 = kva1;
        if (k + 1 < 16) {
            int offn = s_off[p][k + 1];
            kva0 = *reinterpret_cast<const float4*>(gbase + offn);
            kva1 = *reinterpret_cast<const float4*>(gbase + offn + 16);
        }

        // 8-channel partial dot (key lanes); butterfly over the 4-lane group
        float s = fmaf(q0.x, kv0.x, fmaf(q0.y, kv0.y,
                  fmaf(q0.z, kv0.z, fmaf(q0.w, kv0.w,
                  fmaf(q1.x, kv1.x, fmaf(q1.y, kv1.y,
                  fmaf(q1.z, kv1.z, q1.w * kv1.w)))))));
        s *= keysel;
        s += __shfl_xor_sync(FULL, s, 1);
        s += __shfl_xor_sync(FULL, s, 2);   // all 4 lanes: full dot
        if (k == 0) s0 = s;
        float e = __expf(s - s0);           // e = 1 for k == 0
        if ((k >> 2) == L) my_e[k & 3] = e; // compile-time k: ISETP + SEL
        sum += e;
        acc0.x = fmaf(e, kv0.x, acc0.x);    // value lanes accumulate
        acc0.y = fmaf(e, kv0.y, acc0.y);
        acc0.z = fmaf(e, kv0.z, acc0.z);
        acc0.w = fmaf(e, kv0.w, acc0.w);
        acc1.x = fmaf(e, kv1.x, acc1.x);
        acc1.y = fmaf(e, kv1.y, acc1.y);
        acc1.z = fmaf(e, kv1.z, acc1.z);
        acc1.w = fmaf(e, kv1.w, acc1.w);
    }
    const float inv = 1.0f / sum;

    // --- centrality: lane L owns neighbors 4L..4L+3 ---
    if (cent != nullptr) {
        #pragma unroll
        for (int i = 0; i < 4; i++)
            atomicAdd(&cent[bgN + (size_t)mi[i]], my_e[i] * inv);
    }

    // --- feature: lanes 2-3 hold value halves (lane2: ch0-7, lane3: ch8-15) ---
    if (L >= 2) {
        int c0 = (L - 2) * 8;
        ftile[p][c0 + 0] = acc0.x * inv;
        ftile[p][c0 + 1] = acc0.y * inv;
        ftile[p][c0 + 2] = acc0.z * inv;
        ftile[p][c0 + 3] = acc0.w * inv;
        ftile[p][c0 + 4] = acc1.x * inv;
        ftile[p][c0 + 5] = acc1.y * inv;
        ftile[p][c0 + 6] = acc1.z * inv;
        ftile[p][c0 + 7] = acc1.w * inv;
    }
    __syncthreads();

    // --- coalesced write in (B, C, N) layout: 16 rows x 64 points ---
    float* fout = out + ((size_t)b * C + (size_t)g * D) * N + n0;
    #pragma unroll
    for (int r = 0; r < 4; r++) {
        int e = tid + r * 256;
        int j = e >> 6, nn = e & 63;
        fout[(size_t)j * N + nn] = ftile[nn][j];
    }
}

// ---------------------------------------------------------------------------
// Launch
// ---------------------------------------------------------------------------
extern "C" void kernel_launch(void* const* d_in, const int* in_sizes, int n_in,
                              void* d_out, int out_size)
{
    // Resolve inputs by element count (robust to ordering)
    const float* qk  = nullptr;
    const float* val = nullptr;
    const void*  idx = nullptr;

    for (int i = 0; i < n_in; i++) {
        if (in_sizes[i] == FEAT_ELEMS) {
            if (qk == nullptr)       qk  = (const float*)d_in[i];
            else if (val == nullptr) val = (const float*)d_in[i];
        } else if (in_sizes[i] == IDX_ELEMS) {
            idx = d_in[i];
        }
    }
    if (qk == nullptr || val == nullptr || idx == nullptr) {
        qk  = (const float*)d_in[4];
        val = (const float*)d_in[5];
        idx = d_in[6];
    }

    float* out  = (float*)d_out;                   // feature (B*C*N) first
    float* cent = nullptr;                         // then centrality (B*G*N)
    if (out_size >= FEAT_ELEMS + CENT_ELEMS)
        cent = out + (size_t)FEAT_ELEMS;

    transpose_kernel<<<TBLOCKS, 256>>>(qk, val, (const unsigned int*)idx, cent);
    attn_kernel<<<ABLOCKS, 256>>>(idx, out, cent);
}

// round 15
// speedup vs baseline: 1.1622x; 1.1622x over previous
#include <cuda_runtime.h>
#include <cstddef>

// Problem constants (fixed by setup_inputs)
constexpr int B = 8;
constexpr int C = 144;
constexpr int N = 4096;
constexpr int K = 16;
constexpr int G = 9;
constexpr int D = 16;          // C / G
constexpr int NTILE = 64;      // points per transpose block
constexpr int NBLK_N = N / NTILE;

constexpr int FEAT_ELEMS = B * C * N;      // 4718592
constexpr int CENT_ELEMS = B * G * N;      // 294912
constexpr int IDX_ELEMS  = B * N * K;      // 524288
constexpr int TBLOCKS    = B * G * NBLK_N; // 4608 (= CENT_ELEMS / 64)

constexpr int PTS      = 64;               // points per attn inner iteration
constexpr int CHUNKS   = 8;                // blocks per bg slab
constexpr int CHUNK_PTS = N / CHUNKS;      // 512 points per block
constexpr int ITERS    = CHUNK_PTS / PTS;  // 8 inner iterations
constexpr int ABLOCKS  = B * G * CHUNKS;   // 576

// Fused scratch: per point one 128B row = [key(16 floats) | value(16 floats)].
__device__ __align__(128) float g_qkv[(size_t)B * G * N * 32];

// Index-dtype flag: 1 if idx_knn is int64, 0 if int32.
__device__ int g_idx_is64;

// ---------------------------------------------------------------------------
// Transpose (B, C, N) -> fused (B*G, N, 32) rows, zero the centrality region,
// and (block 0 only) detect the idx dtype.
// ---------------------------------------------------------------------------
__global__ void __launch_bounds__(256) transpose_kernel(
    const float* __restrict__ qk, const float* __restrict__ val,
    const unsigned int* __restrict__ idx_raw,
    float* __restrict__ cent)
{
    __shared__ float tile[D][NTILE + 1];
    __shared__ unsigned int s_any;

    const int blk   = blockIdx.x;
    const int ntile = blk % NBLK_N;
    const int bg    = blk / NBLK_N;
    const int g     = bg % G;
    const int b     = bg / G;
    const int n0    = ntile * NTILE;
    const int tid   = threadIdx.x;

    // ---- block 0: idx dtype detection (odd words all zero => int64) ----
    if (blk == 0) {
        if (tid == 0) s_any = 0u;
        __syncthreads();
        unsigned int v = idx_raw[2 * tid + 1] |
                         idx_raw[2 * (tid + 256) + 1] |
                         idx_raw[2 * (tid + 512) + 1] |
                         idx_raw[2 * (tid + 768) + 1];
        if (v) atomicOr(&s_any, 1u);
        __syncthreads();
        if (tid == 0) g_idx_is64 = (s_any == 0u) ? 1 : 0;
    }

    // ---- zero this block's 64-element slice of centrality ----
    if (cent != nullptr && tid < 64)
        cent[(size_t)blk * 64 + tid] = 0.0f;

    const size_t src_off = ((size_t)b * C + (size_t)g * D) * N + n0;
    float* dst = g_qkv + ((size_t)bg * N + n0) * 32;

    {   // queryandkey -> row offset [0:16)
        const float* src = qk + src_off;
        #pragma unroll
        for (int r = 0; r < 4; r++) {
            int e = tid + r * 256;
            int j = e >> 6, nn = e & 63;
            tile[j][nn] = src[(size_t)j * N + nn];
        }
        __syncthreads();
        #pragma unroll
        for (int r = 0; r < 4; r++) {
            int e = tid + r * 256;
            int nn = e >> 4, j = e & 15;
            dst[nn * 32 + j] = tile[j][nn];
        }
        __syncthreads();
    }
    {   // value -> row offset [16:32)
        const float* src = val + src_off;
        #pragma unroll
        for (int r = 0; r < 4; r++) {
            int e = tid + r * 256;
            int j = e >> 6, nn = e & 63;
            tile[j][nn] = src[(size_t)j * N + nn];
        }
        __syncthreads();
        #pragma unroll
        for (int r = 0; r < 4; r++) {
            int e = tid + r * 256;
            int nn = e >> 4, j = e & 15;
            dst[nn * 32 + 16 + j] = tile[j][nn];
        }
    }
}

// ---------------------------------------------------------------------------
// Fused attention, 512 points per block (8 iterations of the 4-lane core).
// Centrality contributions accumulate in a per-block smem array (SM-side
// atomics) and flush ONCE as 4096 coalesced global adds — cutting the
// scattered-atomic LTS traffic ~16x (R10-R14 plateau = LTS bandwidth wall).
// 4-lane core: lane 0: key[0:8]  lane 1: key[8:16]  lane 2/3: value halves;
// one 128B row per neighbor, butterfly xor1+xor2 dot, first-logit softmax.
// ---------------------------------------------------------------------------
__global__ void __launch_bounds__(256, 4) attn_kernel(
    const void* __restrict__ idx_raw,
    float* __restrict__ out,           // feature region
    float* __restrict__ cent)          // centrality region (may be null)
{
    __shared__ float s_cent[N];         // 16KB per-block centrality accumulator
    __shared__ int   s_off[PTS][17];    // [point][k]: neighbor byte offsets
    __shared__ float ftile[PTS][D + 1];

    const int blk   = blockIdx.x;
    const int chunk = blk % CHUNKS;
    const int bg    = blk / CHUNKS;
    const int g     = bg % G;
    const int b     = bg / G;

    const int tid = threadIdx.x;
    const int p   = tid >> 2;           // point within iteration (0..63)
    const int L   = tid & 3;            // lane within point (0..3)
    const unsigned FULL = 0xffffffffu;

    const float keysel = (L < 2) ? 1.0f : 0.0f;   // value lanes contribute 0
    const size_t bgN = (size_t)bg * N;
    const bool do_cent = (cent != nullptr);

    // ---- zero the smem centrality accumulator ----
    float4* sc4 = reinterpret_cast<float4*>(s_cent);
    #pragma unroll
    for (int r = 0; r < 4; r++)
        sc4[tid + r * 256] = make_float4(0.f, 0.f, 0.f, 0.f);
    __syncthreads();

    // Gather base pointer: folds bg-slab and this lane's 32B sub-offset.
    const char* gbase = reinterpret_cast<const char*>(g_qkv)
                      + bgN * 128 + (size_t)L * 32;
    const int is64 = g_idx_is64;

    for (int it = 0; it < ITERS; it++) {
        const int n0 = chunk * CHUNK_PTS + it * PTS;
        const int n  = n0 + p;

        // --- lane L loads neighbors 4L..4L+3 (dtype-dispatched), clamp ---
        const size_t ibase = ((size_t)b * N + n) * K + 4 * L;
        int mi[4];
        if (is64) {
            const long long* ip = reinterpret_cast<const long long*>(idx_raw) + ibase;
            longlong2 e0 = *reinterpret_cast<const longlong2*>(ip);
            longlong2 e1 = *reinterpret_cast<const longlong2*>(ip + 2);
            mi[0] = (int)e0.x; mi[1] = (int)e0.y; mi[2] = (int)e1.x; mi[3] = (int)e1.y;
        } else {
            int4 e = *reinterpret_cast<const int4*>(
                reinterpret_cast<const int*>(idx_raw) + ibase);
            mi[0] = e.x; mi[1] = e.y; mi[2] = e.z; mi[3] = e.w;
        }
        #pragma unroll
        for (int i = 0; i < 4; i++) {
            mi[i] = min(max(mi[i], 0), N - 1);
            s_off[p][4 * L + i] = mi[i] << 7;   // 128 bytes per point row
        }
        __syncwarp();

        // --- query halves (key lanes use q[0:8]/q[8:16]; value lanes mirror) ---
        const char* qrow = reinterpret_cast<const char*>(g_qkv)
                         + (bgN + n) * 128 + (size_t)(L & 1) * 32;
        const float4 q0 = *reinterpret_cast<const float4*>(qrow);
        const float4 q1 = *reinterpret_cast<const float4*>(qrow + 16);

        // --- single pass, depth-2 pipelined gathers (2 float4 per k) ---
        float s0 = 0.0f;                    // shift = first logit
        float sum = 0.0f;
        float my_e[4] = {0.f, 0.f, 0.f, 0.f};
        float4 acc0 = make_float4(0.f, 0.f, 0.f, 0.f);
        float4 acc1 = make_float4(0.f, 0.f, 0.f, 0.f);

        float4 kva0 = *reinterpret_cast<const float4*>(gbase + s_off[p][0]);
        float4 kva1 = *reinterpret_cast<const float4*>(gbase + s_off[p][0] + 16);

        #pragma unroll
        for (int k = 0; k < 16; k++) {
            float4 kv0 = kva0, kv1 = kva1;
            if (k + 1 < 16) {
                int offn = s_off[p][k + 1];
                kva0 = *reinterpret_cast<const float4*>(gbase + offn);
                kva1 = *reinterpret_cast<const float4*>(gbase + offn + 16);
            }

            // 8-channel partial dot (key lanes); butterfly over the quad
            float s = fmaf(q0.x, kv0.x, fmaf(q0.y, kv0.y,
                      fmaf(q0.z, kv0.z, fmaf(q0.w, kv0.w,
                      fmaf(q1.x, kv1.x, fmaf(q1.y, kv1.y,
                      fmaf(q1.z, kv1.z, q1.w * kv1.w)))))));
            s *= keysel;
            s += __shfl_xor_sync(FULL, s, 1);
            s += __shfl_xor_sync(FULL, s, 2);   // all 4 lanes: full dot
            if (k == 0) s0 = s;
            float e = __expf(s - s0);           // e = 1 for k == 0
            if ((k >> 2) == L) my_e[k & 3] = e; // compile-time k: ISETP + SEL
            sum += e;
            acc0.x = fmaf(e, kv0.x, acc0.x);    // value lanes accumulate
            acc0.y = fmaf(e, kv0.y, acc0.y);
            acc0.z = fmaf(e, kv0.z, acc0.z);
            acc0.w = fmaf(e, kv0.w, acc0.w);
            acc1.x = fmaf(e, kv1.x, acc1.x);
            acc1.y = fmaf(e, kv1.y, acc1.y);
            acc1.z = fmaf(e, kv1.z, acc1.z);
            acc1.w = fmaf(e, kv1.w, acc1.w);
        }
        const float inv = 1.0f / sum;

        // --- centrality: accumulate into block-local smem (cheap SM-side) ---
        if (do_cent) {
            #pragma unroll
            for (int i = 0; i < 4; i++)
                atomicAdd(&s_cent[mi[i]], my_e[i] * inv);
        }

        // --- feature: lanes 2-3 hold value halves ---
        if (L >= 2) {
            int c0 = (L - 2) * 8;
            ftile[p][c0 + 0] = acc0.x * inv;
            ftile[p][c0 + 1] = acc0.y * inv;
            ftile[p][c0 + 2] = acc0.z * inv;
            ftile[p][c0 + 3] = acc0.w * inv;
            ftile[p][c0 + 4] = acc1.x * inv;
            ftile[p][c0 + 5] = acc1.y * inv;
            ftile[p][c0 + 6] = acc1.z * inv;
            ftile[p][c0 + 7] = acc1.w * inv;
        }
        __syncthreads();

        // --- coalesced write in (B, C, N) layout: 16 rows x 64 points ---
        float* fout = out + ((size_t)b * C + (size_t)g * D) * N + n0;
        #pragma unroll
        for (int r = 0; r < 4; r++) {
            int e = tid + r * 256;
            int j = e >> 6, nn = e & 63;
            fout[(size_t)j * N + nn] = ftile[nn][j];
        }
        __syncthreads();   // ftile reused next iteration
    }

    // ---- flush: 4096 coalesced global adds (8 slabs share each cent row) ----
    if (do_cent) {
        float* cbase = cent + bgN;
        #pragma unroll
        for (int r = 0; r < 16; r++) {
            int i = tid + r * 256;
            atomicAdd(&cbase[i], s_cent[i]);
        }
    }
}

// ---------------------------------------------------------------------------
// Launch
// ---------------------------------------------------------------------------
extern "C" void kernel_launch(void* const* d_in, const int* in_sizes, int n_in,
                              void* d_out, int out_size)
{
    // Resolve inputs by element count (robust to ordering)
    const float* qk  = nullptr;
    const float* val = nullptr;
    const void*  idx = nullptr;

    for (int i = 0; i < n_in; i++) {
        if (in_sizes[i] == FEAT_ELEMS) {
            if (qk == nullptr)       qk  = (const float*)d_in[i];
            else if (val == nullptr) val = (const float*)d_in[i];
        } else if (in_sizes[i] == IDX_ELEMS) {
            idx = d_in[i];
        }
    }
    if (qk == nullptr || val == nullptr || idx == nullptr) {
        qk  = (const float*)d_in[4];
        val = (const float*)d_in[5];
        idx = d_in[6];
    }

    float* out  = (float*)d_out;                   // feature (B*C*N) first
    float* cent = nullptr;                         // then centrality (B*G*N)
    if (out_size >= FEAT_ELEMS + CENT_ELEMS)
        cent = out + (size_t)FEAT_ELEMS;

    transpose_kernel<<<TBLOCKS, 256>>>(qk, val, (const unsigned int*)idx, cent);
    attn_kernel<<<ABLOCKS, 256>>>(idx, out, cent);
}